// round 1
// baseline (speedup 1.0000x reference)
#include <cuda_runtime.h>
#include <cuda_bf16.h>

#define B 4
#define C 128
#define HH 64
#define WW 64
#define CM 64
#define CO 100
#define HO 128
#define WO 128

// scratch (static device globals — no runtime allocation)
__device__ float g_wc[C*CM];          // comp weights transposed+BN-scaled: [c][m]
__device__ float g_we[CM*9*CO];       // enc weights transposed+BN-scaled:  [c][tap][o]
__device__ float g_W1[B*CM*HH*WW];    // conv1x1+SiLU activations
__device__ float g_W2[B*CO*HH*WW];    // conv3x3+BN logits

// ---------------------------------------------------------------------------
// K0: fold BN scale into weights and transpose for coalesced smem staging
// ---------------------------------------------------------------------------
__global__ void k0_prep(const float* __restrict__ cw, const float* __restrict__ cg,
                        const float* __restrict__ ew, const float* __restrict__ eg) {
    int i = blockIdx.x * blockDim.x + threadIdx.x;
    const float s = rsqrtf(1.0f + 1e-5f);
    if (i < C*CM) {
        int c = i >> 6, m = i & 63;
        g_wc[i] = cw[m*C + c] * (cg[m] * s);
    }
    if (i < CM*9*CO) {
        int c = i / 900, r = i - c*900, t = r / 100, o = r - t*100;
        g_we[i] = ew[(o*CM + c)*9 + t] * (eg[o] * s);
    }
}

// ---------------------------------------------------------------------------
// K1: 1x1 conv (128->64) + BN bias + SiLU.  GEMM 64 x 16384, K=128.
// Block: 256 thr = 16 m-groups(x4) x 16 px-groups(x8); tile 64m x 128px.
// ---------------------------------------------------------------------------
__global__ __launch_bounds__(256) void k1_comp(const float* __restrict__ X,
                                               const float* __restrict__ cb) {
    __shared__ float xs[16*128];
    __shared__ float ws[16*64];
    int px0 = blockIdx.x * 128;
    int b   = px0 >> 12;
    int hw0 = px0 & 4095;
    int tid = threadIdx.x, mg = tid >> 4, pg = tid & 15;

    float acc[4][8];
#pragma unroll
    for (int o = 0; o < 4; o++)
#pragma unroll
        for (int p = 0; p < 8; p++) acc[o][p] = 0.f;

    for (int c0 = 0; c0 < C; c0 += 16) {
        __syncthreads();
#pragma unroll
        for (int k = 0; k < 8; k++) {
            int idx = tid + k*256;
            xs[idx] = X[(b*C + c0 + (idx >> 7))*4096 + hw0 + (idx & 127)];
        }
#pragma unroll
        for (int k = 0; k < 4; k++) {
            int idx = tid + k*256;
            ws[idx] = g_wc[c0*64 + idx];
        }
        __syncthreads();
#pragma unroll
        for (int c = 0; c < 16; c++) {
            float4 w  = *(const float4*)&ws[c*64  + mg*4];
            float4 xa = *(const float4*)&xs[c*128 + pg*8];
            float4 xb = *(const float4*)&xs[c*128 + pg*8 + 4];
            float xv[8] = {xa.x,xa.y,xa.z,xa.w, xb.x,xb.y,xb.z,xb.w};
            float wv[4] = {w.x, w.y, w.z, w.w};
#pragma unroll
            for (int o = 0; o < 4; o++)
#pragma unroll
                for (int p = 0; p < 8; p++) acc[o][p] += wv[o]*xv[p];
        }
    }
#pragma unroll
    for (int o = 0; o < 4; o++) {
        int m = mg*4 + o;
        float bias = cb[m];
#pragma unroll
        for (int p = 0; p < 8; p++) {
            float z = acc[o][p] + bias;
            float y = z / (1.0f + __expf(-z));           // SiLU
            g_W1[(b*CM + m)*4096 + hw0 + pg*8 + p] = y;
        }
    }
}

// ---------------------------------------------------------------------------
// K2: 3x3 conv (64->100), pad 1, + BN bias.  The dominant kernel (943 M MAC).
// Block: 200 thr = 25 o-groups(x4) x 8 row-groups(x8 px); tile 100o x 64px (8x8).
// Weights pre-transposed [c][tap][o] -> v4 smem loads; x register-cached 3x10.
// ---------------------------------------------------------------------------
__global__ __launch_bounds__(200) void k2_enc(const float* __restrict__ eb) {
    __shared__ float xs[8*120];    // [c][10 rows][pitch 12]
    __shared__ float ws[8*900];    // [c][9 taps][100 o]
    int blk  = blockIdx.x;
    int b    = blk >> 6;
    int tile = blk & 63;
    int y0   = (tile >> 3)*8, x0 = (tile & 7)*8;
    int tid  = threadIdx.x;
    int og   = tid >> 3, pg = tid & 7;

    float acc[4][8];
#pragma unroll
    for (int o = 0; o < 4; o++)
#pragma unroll
        for (int p = 0; p < 8; p++) acc[o][p] = 0.f;

    for (int c0 = 0; c0 < CM; c0 += 8) {
        __syncthreads();
        for (int k = tid; k < 800; k += 200) {
            int c = k / 100, p = k - c*100, r = p / 10, cl = p - r*10;
            int y = y0 + r - 1, x = x0 + cl - 1;
            float v = 0.f;
            if ((unsigned)y < 64u && (unsigned)x < 64u)
                v = g_W1[(b*CM + c0 + c)*4096 + y*64 + x];
            xs[c*120 + r*12 + cl] = v;
        }
        for (int k = tid; k < 7200; k += 200) ws[k] = g_we[c0*900 + k];
        __syncthreads();

#pragma unroll
        for (int c = 0; c < 8; c++) {
            float xr[3][10];
#pragma unroll
            for (int r = 0; r < 3; r++) {
                const float* row = &xs[c*120 + (pg + r)*12];
                float4 a  = *(const float4*)row;
                float4 b4 = *(const float4*)(row + 4);
                float2 c2 = *(const float2*)(row + 8);
                xr[r][0]=a.x;  xr[r][1]=a.y;  xr[r][2]=a.z;  xr[r][3]=a.w;
                xr[r][4]=b4.x; xr[r][5]=b4.y; xr[r][6]=b4.z; xr[r][7]=b4.w;
                xr[r][8]=c2.x; xr[r][9]=c2.y;
            }
#pragma unroll
            for (int t = 0; t < 9; t++) {
                int ti = t / 3, tj = t - ti*3;
                float4 w = *(const float4*)&ws[c*900 + t*100 + og*4];
#pragma unroll
                for (int p = 0; p < 8; p++) {
                    float xv = xr[ti][p + tj];
                    acc[0][p] += w.x*xv;
                    acc[1][p] += w.y*xv;
                    acc[2][p] += w.z*xv;
                    acc[3][p] += w.w*xv;
                }
            }
        }
    }
    int rowbase = (y0 + pg)*64 + x0;
#pragma unroll
    for (int o = 0; o < 4; o++) {
        int oo = og*4 + o;
        float bias = eb[oo];
#pragma unroll
        for (int p = 0; p < 8; p++)
            g_W2[(b*CO + oo)*4096 + rowbase + p] = acc[o][p] + bias;
    }
}

// ---------------------------------------------------------------------------
// K3: pixel-shuffle + softmax(25) + CARAFE weighted gather, fused.
// For low-res pixel (y0,x0): subpixel s=(r1*2+r2) weight k comes from
// W2 channel k*4+s; all 4 subpixels share the same 5x5 X neighborhood.
// Block: 128 thr = one 16x8 low-res tile; each thread holds all 100 softmax
// weights in registers and loops 64 channels (grid split in 2 channel halves).
// ---------------------------------------------------------------------------
__global__ __launch_bounds__(128) void k3_carafe(const float* __restrict__ X,
                                                 float* __restrict__ out) {
    __shared__ float xs[4*240];    // [c][12 rows][pitch 20]
    int blk    = blockIdx.x;
    int chalf  = blk >> 7;
    int tileid = blk & 127;
    int b  = tileid >> 5;
    int t  = tileid & 31;
    int ty = t >> 2, tx = t & 3;
    int tid = threadIdx.x;
    int py  = tid >> 4, pxl = tid & 15;
    int y0g = ty*8 + py, x0g = tx*16 + pxl;

    // --- softmax weights for all 4 subpixels, kept in registers ---
    float w[4][25];
    {
        const float* base = g_W2 + (size_t)b*CO*4096 + y0g*64 + x0g;
#pragma unroll
        for (int k = 0; k < 25; k++)
#pragma unroll
            for (int s = 0; s < 4; s++)
                w[s][k] = base[(k*4 + s)*4096];
#pragma unroll
        for (int s = 0; s < 4; s++) {
            float m = w[s][0];
#pragma unroll
            for (int k = 1; k < 25; k++) m = fmaxf(m, w[s][k]);
            float sum = 0.f;
#pragma unroll
            for (int k = 0; k < 25; k++) { float e = __expf(w[s][k] - m); w[s][k] = e; sum += e; }
            float inv = 1.0f / sum;
#pragma unroll
            for (int k = 0; k < 25; k++) w[s][k] *= inv;
        }
    }

    int cbase = chalf*64;
    int ybase = ty*8 - 2, xbase = tx*16 - 2;
    for (int c0 = 0; c0 < 64; c0 += 4) {
        __syncthreads();
        for (int k = tid; k < 960; k += 128) {
            int c = k / 240, p = k - c*240, r = p / 20, cl = p - r*20;
            int y = ybase + r, x = xbase + cl;
            float v = 0.f;
            if ((unsigned)y < 64u && (unsigned)x < 64u)
                v = X[((b*C + cbase + c0 + c)*64 + y)*64 + x];
            xs[c*240 + r*20 + cl] = v;
        }
        __syncthreads();
#pragma unroll
        for (int c = 0; c < 4; c++) {
            float a0 = 0.f, a1 = 0.f, a2 = 0.f, a3 = 0.f;
            const float* xp = &xs[c*240 + py*20 + pxl];
#pragma unroll
            for (int i = 0; i < 5; i++)
#pragma unroll
                for (int j = 0; j < 5; j++) {
                    float xv = xp[i*20 + j];
                    int kk = i*5 + j;
                    a0 += xv*w[0][kk];
                    a1 += xv*w[1][kk];
                    a2 += xv*w[2][kk];
                    a3 += xv*w[3][kk];
                }
            int ch = cbase + c0 + c;
            size_t ob = ((size_t)(b*C + ch)*HO + 2*y0g)*WO + 2*x0g;
            *(float2*)&out[ob]      = make_float2(a0, a1);
            *(float2*)&out[ob + WO] = make_float2(a2, a3);
        }
    }
}

// ---------------------------------------------------------------------------
extern "C" void kernel_launch(void* const* d_in, const int* in_sizes, int n_in,
                              void* d_out, int out_size) {
    const float* X      = (const float*)d_in[0];
    const float* comp_w = (const float*)d_in[1];
    const float* comp_g = (const float*)d_in[2];
    const float* comp_b = (const float*)d_in[3];
    const float* enc_w  = (const float*)d_in[4];
    const float* enc_g  = (const float*)d_in[5];
    const float* enc_b  = (const float*)d_in[6];
    float* out = (float*)d_out;

    k0_prep  <<<225, 256>>>(comp_w, comp_g, enc_w, enc_g);
    k1_comp  <<<128, 256>>>(X, comp_b);
    k2_enc   <<<256, 200>>>(enc_b);
    k3_carafe<<<256, 128>>>(X, out);
}

// round 2
// speedup vs baseline: 1.2231x; 1.2231x over previous
#include <cuda_runtime.h>
#include <cuda_bf16.h>

#define B 4
#define C 128
#define CM 64
#define CO 100
#define HO 128
#define WO 128

typedef unsigned long long u64;

// packed f32x2 helpers (FFMA2 — ptxas never emits these from C++)
__device__ __forceinline__ u64 pk(float lo, float hi) {
    u64 r; asm("mov.b64 %0, {%1,%2};" : "=l"(r) : "f"(lo), "f"(hi)); return r;
}
__device__ __forceinline__ float2 upk(u64 v) {
    float2 f; asm("mov.b64 {%0,%1}, %2;" : "=f"(f.x), "=f"(f.y) : "l"(v)); return f;
}
#define FMA2(d,a,b) asm("fma.rn.f32x2 %0, %1, %2, %0;" : "+l"(d) : "l"(a), "l"(b))
#define MUL2(d,a,b) asm("mul.rn.f32x2 %0, %1, %2;" : "=l"(d) : "l"(a), "l"(b))

// scratch (static device globals — no runtime allocation)
__device__ float g_wc[C*CM];          // comp weights transposed+BN-scaled: [c][m]
__device__ float g_we[CM*9*CO];       // enc weights transposed+BN-scaled:  [c][tap][o]
__device__ float g_W1[B*CM*64*64];    // conv1x1+SiLU activations
__device__ float g_W2[B*CO*64*64];    // conv3x3+BN logits

// ---------------------------------------------------------------------------
// K0: fold BN scale into weights and transpose
// ---------------------------------------------------------------------------
__global__ void k0_prep(const float* __restrict__ cw, const float* __restrict__ cg,
                        const float* __restrict__ ew, const float* __restrict__ eg) {
    int i = blockIdx.x * blockDim.x + threadIdx.x;
    const float s = rsqrtf(1.0f + 1e-5f);
    if (i < C*CM) {
        int c = i >> 6, m = i & 63;
        g_wc[i] = cw[m*C + c] * (cg[m] * s);
    }
    if (i < CM*9*CO) {
        int c = i / 900, r = i - c*900, t = r / 100, o = r - t*100;
        g_we[i] = ew[(o*CM + c)*9 + t] * (eg[o] * s);
    }
}

// ---------------------------------------------------------------------------
// K1: 1x1 conv (128->64) + BN bias + SiLU.  Tile 64m x 64px, grid 256.
// Block 256 = 16 mg(4o) x 16 pg(4px).  FFMA2 along px pairs.
// ---------------------------------------------------------------------------
__global__ __launch_bounds__(256) void k1_comp(const float* __restrict__ X,
                                               const float* __restrict__ cb) {
    __shared__ float xs[16*64];
    __shared__ float ws[16*64];
    int blk = blockIdx.x;
    int b   = blk >> 6;
    int hw0 = (blk & 63) * 64;
    int tid = threadIdx.x, mg = tid >> 4, pxl = (tid & 15) * 4;

    u64 acc[4][2];
#pragma unroll
    for (int o = 0; o < 4; o++) { acc[o][0] = 0ull; acc[o][1] = 0ull; }

    for (int c0 = 0; c0 < C; c0 += 16) {
        __syncthreads();
        {   // 1 float4 per thread each
            int c = tid >> 4, px = (tid & 15) * 4;
            *(float4*)&xs[c*64 + px] =
                *(const float4*)&X[(b*C + c0 + c)*4096 + hw0 + px];
            *(float4*)&ws[tid*4] = *(const float4*)&g_wc[c0*64 + tid*4];
        }
        __syncthreads();
#pragma unroll
        for (int c = 0; c < 16; c++) {
            float4 w = *(const float4*)&ws[c*64 + mg*4];
            u64 w0 = pk(w.x,w.x), w1 = pk(w.y,w.y), w2 = pk(w.z,w.z), w3 = pk(w.w,w.w);
            u64 xa = *(const u64*)&xs[c*64 + pxl];
            u64 xb = *(const u64*)&xs[c*64 + pxl + 2];
            FMA2(acc[0][0], w0, xa); FMA2(acc[0][1], w0, xb);
            FMA2(acc[1][0], w1, xa); FMA2(acc[1][1], w1, xb);
            FMA2(acc[2][0], w2, xa); FMA2(acc[2][1], w2, xb);
            FMA2(acc[3][0], w3, xa); FMA2(acc[3][1], w3, xb);
        }
    }
#pragma unroll
    for (int o = 0; o < 4; o++) {
        int m = mg*4 + o;
        float bias = cb[m];
        float* dst = &g_W1[(b*CM + m)*4096 + hw0 + pxl];
#pragma unroll
        for (int j = 0; j < 2; j++) {
            float2 v = upk(acc[o][j]);
            float z0 = v.x + bias, z1 = v.y + bias;
            float y0 = z0 / (1.0f + __expf(-z0));
            float y1 = z1 / (1.0f + __expf(-z1));
            *(float2*)(dst + j*2) = make_float2(y0, y1);
        }
    }
}

// ---------------------------------------------------------------------------
// K2: 3x3 conv (64->100) + BN bias.  Tile 100o x (4x8)px, grid 512.
// Block 200 = 25 og(4o) x 8 pg(4px).  FFMA2 along px pairs; x pairs via
// aligned LDS.64 (+1 shuffle pack per odd pair), weights broadcast-packed.
// ---------------------------------------------------------------------------
__global__ __launch_bounds__(200, 4) void k2_enc(const float* __restrict__ eb) {
    __shared__ float xs[8*6*12];   // [c][6 rows][pitch 12]
    __shared__ float ws[8*900];    // [c][9 taps][100 o]
    int blk  = blockIdx.x;
    int b    = blk >> 7;
    int tile = blk & 127;
    int y0   = (tile >> 3)*4, x0 = (tile & 7)*8;
    int tid  = threadIdx.x;
    int og   = tid >> 3, pg = tid & 7;
    int prow = pg >> 1, pcol = (pg & 1)*4;

    u64 acc[4][2];
#pragma unroll
    for (int o = 0; o < 4; o++) { acc[o][0] = 0ull; acc[o][1] = 0ull; }

    for (int c0 = 0; c0 < CM; c0 += 8) {
        __syncthreads();
        for (int k = tid; k < 480; k += 200) {
            int c = k / 60, p = k - c*60, r = p / 10, cl = p - r*10;
            int y = y0 + r - 1, x = x0 + cl - 1;
            float v = 0.f;
            if ((unsigned)y < 64u && (unsigned)x < 64u)
                v = g_W1[(b*CM + c0 + c)*4096 + y*64 + x];
            xs[c*72 + r*12 + cl] = v;
        }
        {
            const float4* src = (const float4*)&g_we[c0*900];
            float4* dst = (float4*)ws;
#pragma unroll
            for (int j = 0; j < 9; j++) dst[tid + j*200] = src[tid + j*200];
        }
        __syncthreads();

#pragma unroll
        for (int c = 0; c < 8; c++) {
#pragma unroll
            for (int ti = 0; ti < 3; ti++) {
                const float* rb = &xs[c*72 + (prow + ti)*12 + pcol];
                u64 E0 = *(const u64*)rb;
                u64 E1 = *(const u64*)(rb + 2);
                u64 E2 = *(const u64*)(rb + 4);
                float2 f0 = upk(E0), f1 = upk(E1), f2 = upk(E2);
                u64 O0 = pk(f0.y, f1.x);
                u64 O1 = pk(f1.y, f2.x);
#pragma unroll
                for (int tj = 0; tj < 3; tj++) {
                    u64 xa = (tj == 0) ? E0 : (tj == 1) ? O0 : E1;
                    u64 xb = (tj == 0) ? E1 : (tj == 1) ? O1 : E2;
                    float4 w = *(const float4*)&ws[c*900 + (ti*3 + tj)*100 + og*4];
                    u64 w0 = pk(w.x,w.x), w1 = pk(w.y,w.y);
                    u64 w2 = pk(w.z,w.z), w3 = pk(w.w,w.w);
                    FMA2(acc[0][0], w0, xa); FMA2(acc[0][1], w0, xb);
                    FMA2(acc[1][0], w1, xa); FMA2(acc[1][1], w1, xb);
                    FMA2(acc[2][0], w2, xa); FMA2(acc[2][1], w2, xb);
                    FMA2(acc[3][0], w3, xa); FMA2(acc[3][1], w3, xb);
                }
            }
        }
    }
    int rowbase = (y0 + prow)*64 + x0 + pcol;
#pragma unroll
    for (int o = 0; o < 4; o++) {
        int oo = og*4 + o;
        float bias = eb[oo];
        float* dst = &g_W2[(b*CO + oo)*4096 + rowbase];
        float2 v0 = upk(acc[o][0]);
        float2 v1 = upk(acc[o][1]);
        *(float2*)dst       = make_float2(v0.x + bias, v0.y + bias);
        *(float2*)(dst + 2) = make_float2(v1.x + bias, v1.y + bias);
    }
}

// ---------------------------------------------------------------------------
// K3: pixel-shuffle + softmax(25) + CARAFE weighted gather, fused.
// 4-way channel split (grid 512).  Weights packed as subpixel pairs (w01,w23)
// so the combine is 50 FFMA2 per channel instead of 100 FFMA.
// ---------------------------------------------------------------------------
__global__ __launch_bounds__(128, 4) void k3_carafe(const float* __restrict__ X,
                                                    float* __restrict__ out) {
    __shared__ float xs[4*240];    // [c][12 rows][pitch 20]
    int blk    = blockIdx.x;
    int cq     = blk >> 7;          // channel quarter 0..3
    int tileid = blk & 127;
    int b  = tileid >> 5;
    int t  = tileid & 31;
    int ty = t >> 2, tx = t & 3;
    int tid = threadIdx.x;
    int py  = tid >> 4, pxl = tid & 15;
    int y0g = ty*8 + py, x0g = tx*16 + pxl;

    // --- softmax over 25 taps for all 4 subpixels; packed (s0,s1),(s2,s3) ---
    u64 w01[25], w23[25];
    {
        const float* base = g_W2 + (size_t)b*CO*4096 + y0g*64 + x0g;
        float s0 = 0.f, s1 = 0.f, s2 = 0.f, s3 = 0.f;
#pragma unroll
        for (int k = 0; k < 25; k++) {
            float e0 = __expf(base[(k*4 + 0)*4096]); s0 += e0;
            float e1 = __expf(base[(k*4 + 1)*4096]); s1 += e1;
            w01[k] = pk(e0, e1);
            float e2 = __expf(base[(k*4 + 2)*4096]); s2 += e2;
            float e3 = __expf(base[(k*4 + 3)*4096]); s3 += e3;
            w23[k] = pk(e2, e3);
        }
        u64 i01 = pk(1.0f/s0, 1.0f/s1);
        u64 i23 = pk(1.0f/s2, 1.0f/s3);
#pragma unroll
        for (int k = 0; k < 25; k++) {
            MUL2(w01[k], w01[k], i01);
            MUL2(w23[k], w23[k], i23);
        }
    }

    int cbase = cq*32;
    int ybase = ty*8 - 2, xbase = tx*16 - 2;
    for (int c0 = 0; c0 < 32; c0 += 4) {
        __syncthreads();
        for (int k = tid; k < 960; k += 128) {
            int c = k / 240, p = k - c*240, r = p / 20, cl = p - r*20;
            int y = ybase + r, x = xbase + cl;
            float v = 0.f;
            if ((unsigned)y < 64u && (unsigned)x < 64u)
                v = X[((b*C + cbase + c0 + c)*64 + y)*64 + x];
            xs[c*240 + r*20 + cl] = v;
        }
        __syncthreads();
#pragma unroll
        for (int c = 0; c < 4; c++) {
            u64 a01 = 0ull, a23 = 0ull;
            const float* xp = &xs[c*240 + py*20 + pxl];
#pragma unroll
            for (int i = 0; i < 5; i++)
#pragma unroll
                for (int j = 0; j < 5; j++) {
                    float xv = xp[i*20 + j];
                    u64 xx = pk(xv, xv);
                    int kk = i*5 + j;
                    FMA2(a01, w01[kk], xx);
                    FMA2(a23, w23[kk], xx);
                }
            int ch = cbase + c0 + c;
            size_t ob = ((size_t)(b*C + ch)*HO + 2*y0g)*WO + 2*x0g;
            float2 top = upk(a01), bot = upk(a23);
            *(float2*)&out[ob]      = top;
            *(float2*)&out[ob + WO] = bot;
        }
    }
}

// ---------------------------------------------------------------------------
extern "C" void kernel_launch(void* const* d_in, const int* in_sizes, int n_in,
                              void* d_out, int out_size) {
    const float* X      = (const float*)d_in[0];
    const float* comp_w = (const float*)d_in[1];
    const float* comp_g = (const float*)d_in[2];
    const float* comp_b = (const float*)d_in[3];
    const float* enc_w  = (const float*)d_in[4];
    const float* enc_g  = (const float*)d_in[5];
    const float* enc_b  = (const float*)d_in[6];
    float* out = (float*)d_out;

    k0_prep  <<<225, 256>>>(comp_w, comp_g, enc_w, enc_g);
    k1_comp  <<<256, 256>>>(X, comp_b);
    k2_enc   <<<512, 200>>>(enc_b);
    k3_carafe<<<512, 128>>>(X, out);
}